// round 7
// baseline (speedup 1.0000x reference)
#include <cuda_runtime.h>
#include <cstdint>

#define NN 100000
#define DD 64
#define EE 1600000

// Scratch (__device__ globals per allocation-free rule).
__device__ float g_agg [NN * DD];
__device__ float g_bufA[NN * DD];
__device__ float g_bufB[NN * DD];
__device__ int   g_deg   [NN];
__device__ int   g_rowptr[NN + 1];
__device__ int   g_cursor[NN];
__device__ int   g_col   [EE];

typedef unsigned long long ull;
__device__ __forceinline__ ull pack2(float a, float b) {
    ull r; asm("mov.b64 %0, {%1, %2};" : "=l"(r) : "f"(a), "f"(b)); return r;
}
__device__ __forceinline__ void unpack2(ull v, float& a, float& b) {
    asm("mov.b64 {%0, %1}, %2;" : "=f"(a), "=f"(b) : "l"(v));
}
__device__ __forceinline__ ull fma2(ull a, ull b, ull c) {
    ull r; asm("fma.rn.f32x2 %0, %1, %2, %3;" : "=l"(r) : "l"(a), "l"(b), "l"(c)); return r;
}

// ---------------------------------------------------------------------------
// CSR build
// ---------------------------------------------------------------------------
__global__ void zero_deg_kernel() {
    int i = blockIdx.x * blockDim.x + threadIdx.x;
    if (i < NN) g_deg[i] = 0;
}

__global__ void hist_kernel(const int* __restrict__ ei) {
    int e = blockIdx.x * blockDim.x + threadIdx.x;
    if (e < EE) atomicAdd(&g_deg[ei[EE + e]], 1);
}

__global__ void scan_kernel() {
    __shared__ int sums[1024];
    const int CH = (NN + 1023) / 1024;
    int t = threadIdx.x;
    int base = t * CH;
    int s = 0;
    for (int i = 0; i < CH; i++) {
        int idx = base + i;
        if (idx < NN) s += g_deg[idx];
    }
    sums[t] = s;
    __syncthreads();
    for (int off = 1; off < 1024; off <<= 1) {
        int v = (t >= off) ? sums[t - off] : 0;
        __syncthreads();
        sums[t] += v;
        __syncthreads();
    }
    int prefix = (t == 0) ? 0 : sums[t - 1];
    for (int i = 0; i < CH; i++) {
        int idx = base + i;
        if (idx < NN) {
            int d = g_deg[idx];
            g_rowptr[idx] = prefix;
            g_cursor[idx] = prefix;
            prefix += d;
        }
    }
    if (t == 1023) g_rowptr[NN] = prefix;
}

__global__ void fill_kernel(const int* __restrict__ ei) {
    int e = blockIdx.x * blockDim.x + threadIdx.x;
    if (e < EE) {
        int d = ei[EE + e];
        int p = atomicAdd(&g_cursor[d], 1);
        g_col[p] = ei[e];
    }
}

// ---------------------------------------------------------------------------
// Aggregation gather: warp per dst node, TWO neighbor rows per LDG.128.
// Lanes 0-15 cover neighbor j (float4 chunk c=lane&15), lanes 16-31 neighbor
// j+1. 4 independent float4 accumulators (8 neighbors in flight). Final
// cross-half reduce via shfl_xor(16).
//   out[d] = in[d] + sum_{s in CSR(d)} in[s]
// ---------------------------------------------------------------------------
__global__ __launch_bounds__(256) void agg_kernel(const float* __restrict__ in,
                                                  float* __restrict__ out) {
    int w    = (blockIdx.x * blockDim.x + threadIdx.x) >> 5;
    int lane = threadIdx.x & 31;
    if (w >= NN) return;
    int half = lane >> 4;
    int c    = lane & 15;
    int start = g_rowptr[w];
    int end   = g_rowptr[w + 1];

    const float4* in4 = reinterpret_cast<const float4*>(in);
    float4 a0 = make_float4(0.f, 0.f, 0.f, 0.f);
    float4 a1 = a0, a2 = a0, a3 = a0;
    if (half == 0) a0 = in4[(size_t)w * 16 + c];   // self term, counted once

    for (int i = start; i < end; i += 32) {
        int n   = min(32, end - i);
        int idx = (i + lane < end) ? g_col[i + lane] : 0;
        int j = 0;
        for (; j + 8 <= n; j += 8) {
            int s0 = __shfl_sync(0xffffffffu, idx, j     + half);
            int s1 = __shfl_sync(0xffffffffu, idx, j + 2 + half);
            int s2 = __shfl_sync(0xffffffffu, idx, j + 4 + half);
            int s3 = __shfl_sync(0xffffffffu, idx, j + 6 + half);
            float4 v0 = in4[(size_t)s0 * 16 + c];
            float4 v1 = in4[(size_t)s1 * 16 + c];
            float4 v2 = in4[(size_t)s2 * 16 + c];
            float4 v3 = in4[(size_t)s3 * 16 + c];
            a0.x += v0.x; a0.y += v0.y; a0.z += v0.z; a0.w += v0.w;
            a1.x += v1.x; a1.y += v1.y; a1.z += v1.z; a1.w += v1.w;
            a2.x += v2.x; a2.y += v2.y; a2.z += v2.z; a2.w += v2.w;
            a3.x += v3.x; a3.y += v3.y; a3.z += v3.z; a3.w += v3.w;
        }
        for (; j < n; j += 2) {
            int jj = j + half;
            int s = __shfl_sync(0xffffffffu, idx, (jj < n) ? jj : j);
            if (jj < n) {
                float4 v = in4[(size_t)s * 16 + c];
                a0.x += v.x; a0.y += v.y; a0.z += v.z; a0.w += v.w;
            }
        }
    }
    a0.x += a1.x + a2.x + a3.x;  a0.y += a1.y + a2.y + a3.y;
    a0.z += a1.z + a2.z + a3.z;  a0.w += a1.w + a2.w + a3.w;
    a0.x += __shfl_xor_sync(0xffffffffu, a0.x, 16);
    a0.y += __shfl_xor_sync(0xffffffffu, a0.y, 16);
    a0.z += __shfl_xor_sync(0xffffffffu, a0.z, 16);
    a0.w += __shfl_xor_sync(0xffffffffu, a0.w, 16);
    if (half == 0)
        reinterpret_cast<float4*>(out)[(size_t)w * 16 + c] = a0;
}

// ---------------------------------------------------------------------------
// MLP kernels. Lane owns a full row; rows staged through padded smem.
// Weights read from smem as ulonglong2 (pre-paired for fma2, no pack movs).
// half_gemm: one 32-col half, acc[16] packed f32x2.
// ---------------------------------------------------------------------------
#define STRIDE 66
#define STAGE_WORDS (32 * STRIDE)

__device__ __forceinline__ void half_gemm(const float* __restrict__ ws,
                                          const float* __restrict__ h,
                                          ull* acc, int half) {
#pragma unroll 2
    for (int k = 0; k < DD; k++) {
        float hk = h[k];
        ull h2 = pack2(hk, hk);
#pragma unroll
        for (int jj = 0; jj < 8; jj++) {
            ulonglong2 wv = *reinterpret_cast<const ulonglong2*>(
                ws + k * DD + half * 32 + jj * 4);
            acc[2 * jj]     = fma2(wv.x, h2, acc[2 * jj]);
            acc[2 * jj + 1] = fma2(wv.y, h2, acc[2 * jj + 1]);
        }
    }
}

__device__ __forceinline__ void store_row_relu(float* hrow, ull* mA, ull* mB,
                                               bool relu) {
#pragma unroll
    for (int j = 0; j < 16; j++) {
        float a, b;
        unpack2(mA[j], a, b);
        if (relu) { a = fmaxf(a, 0.f); b = fmaxf(b, 0.f); }
        *reinterpret_cast<float2*>(hrow + 2 * j) = make_float2(a, b);
        unpack2(mB[j], a, b);
        if (relu) { a = fmaxf(a, 0.f); b = fmaxf(b, 0.f); }
        *reinterpret_cast<float2*>(hrow + 32 + 2 * j) = make_float2(a, b);
    }
}

__device__ __forceinline__ void gemm64(const float* ws, const ull* bu,
                                       float* hrow, ull* mA, ull* mB) {
#pragma unroll
    for (int j = 0; j < 16; j++) mA[j] = bu[j];
    half_gemm(ws, hrow, mA, 0);
#pragma unroll
    for (int j = 0; j < 16; j++) mB[j] = bu[16 + j];
    half_gemm(ws, hrow, mB, 1);
}

// Two-GEMM MLP (blocks 0,1): out = relu(relu(in@w1+b1)@w2+b2). 8 warps.
__global__ __launch_bounds__(256, 2) void mlp2_kernel(
        const float* __restrict__ in, float* __restrict__ out,
        const float* __restrict__ w1, const float* __restrict__ b1,
        const float* __restrict__ w2, const float* __restrict__ b2) {
    extern __shared__ float sm[];
    float* ws1 = sm;
    float* ws2 = sm + DD * DD;
    int tid  = threadIdx.x;
    int lane = tid & 31;
    int warp = tid >> 5;
    float* stg = sm + 2 * DD * DD + warp * STAGE_WORDS;

    for (int i = tid; i < DD * DD; i += 256) { ws1[i] = w1[i]; ws2[i] = w2[i]; }

    int rowbase = blockIdx.x * 256 + warp * 32;
#pragma unroll 4
    for (int r = 0; r < 32; r++) {
        int row = rowbase + r;
        float2 v = make_float2(0.f, 0.f);
        if (row < NN)
            v = *reinterpret_cast<const float2*>(in + (size_t)row * DD + 2 * lane);
        *reinterpret_cast<float2*>(stg + r * STRIDE + 2 * lane) = v;
    }
    __syncthreads();

    float* hrow = stg + lane * STRIDE;
    ull mA[16], mB[16];
    gemm64(ws1, reinterpret_cast<const ull*>(b1), hrow, mA, mB);
    store_row_relu(hrow, mA, mB, true);
    gemm64(ws2, reinterpret_cast<const ull*>(b2), hrow, mA, mB);
    store_row_relu(hrow, mA, mB, true);

    __syncwarp();
#pragma unroll 4
    for (int r = 0; r < 32; r++) {
        int row = rowbase + r;
        if (row < NN) {
            float2 v = *reinterpret_cast<const float2*>(stg + r * STRIDE + 2 * lane);
            *reinterpret_cast<float2*>(out + (size_t)row * DD + 2 * lane) = v;
        }
    }
}

// Three-GEMM MLP (block 2 + final linear fused). 7 warps so 3 weight
// matrices + stage fit in <114KB smem at 2 CTAs/SM.
__global__ __launch_bounds__(224, 2) void mlp3_kernel(
        const float* __restrict__ in, float* __restrict__ out,
        const float* __restrict__ w1, const float* __restrict__ b1,
        const float* __restrict__ w2, const float* __restrict__ b2,
        const float* __restrict__ w3, const float* __restrict__ b3) {
    extern __shared__ float sm[];
    float* ws1 = sm;
    float* ws2 = sm + DD * DD;
    float* ws3 = sm + 2 * DD * DD;
    int tid  = threadIdx.x;
    int lane = tid & 31;
    int warp = tid >> 5;
    float* stg = sm + 3 * DD * DD + warp * STAGE_WORDS;

    for (int i = tid; i < DD * DD; i += 224) {
        ws1[i] = w1[i]; ws2[i] = w2[i]; ws3[i] = w3[i];
    }

    int rowbase = blockIdx.x * 224 + warp * 32;
#pragma unroll 4
    for (int r = 0; r < 32; r++) {
        int row = rowbase + r;
        float2 v = make_float2(0.f, 0.f);
        if (row < NN)
            v = *reinterpret_cast<const float2*>(in + (size_t)row * DD + 2 * lane);
        *reinterpret_cast<float2*>(stg + r * STRIDE + 2 * lane) = v;
    }
    __syncthreads();

    float* hrow = stg + lane * STRIDE;
    ull mA[16], mB[16];
    gemm64(ws1, reinterpret_cast<const ull*>(b1), hrow, mA, mB);
    store_row_relu(hrow, mA, mB, true);
    gemm64(ws2, reinterpret_cast<const ull*>(b2), hrow, mA, mB);
    store_row_relu(hrow, mA, mB, true);
    gemm64(ws3, reinterpret_cast<const ull*>(b3), hrow, mA, mB);
    store_row_relu(hrow, mA, mB, false);

    __syncwarp();
#pragma unroll 4
    for (int r = 0; r < 32; r++) {
        int row = rowbase + r;
        if (row < NN) {
            float2 v = *reinterpret_cast<const float2*>(stg + r * STRIDE + 2 * lane);
            *reinterpret_cast<float2*>(out + (size_t)row * DD + 2 * lane) = v;
        }
    }
}

// ---------------------------------------------------------------------------
// Launch
// ---------------------------------------------------------------------------
extern "C" void kernel_launch(void* const* d_in, const int* in_sizes, int n_in,
                              void* d_out, int out_size) {
    const float* x  = (const float*)d_in[0];
    const int*   ei = (const int*)d_in[1];
    const float* w1[3] = {(const float*)d_in[2], (const float*)d_in[6],  (const float*)d_in[10]};
    const float* b1[3] = {(const float*)d_in[3], (const float*)d_in[7],  (const float*)d_in[11]};
    const float* w2[3] = {(const float*)d_in[4], (const float*)d_in[8],  (const float*)d_in[12]};
    const float* b2[3] = {(const float*)d_in[5], (const float*)d_in[9],  (const float*)d_in[13]};
    const float* wf = (const float*)d_in[14];
    const float* bf = (const float*)d_in[15];
    float* out = (float*)d_out;

    float *agg, *bufA, *bufB;
    cudaGetSymbolAddress((void**)&agg,  g_agg);
    cudaGetSymbolAddress((void**)&bufA, g_bufA);
    cudaGetSymbolAddress((void**)&bufB, g_bufB);

    const int SMEM2 = (2 * DD * DD + 8 * STAGE_WORDS) * 4;   // ~100.4 KB
    const int SMEM3 = (3 * DD * DD + 7 * STAGE_WORDS) * 4;   // ~108.3 KB
    static bool attr_done = false;
    if (!attr_done) {
        cudaFuncSetAttribute(mlp2_kernel,
                             cudaFuncAttributeMaxDynamicSharedMemorySize, SMEM2);
        cudaFuncSetAttribute(mlp3_kernel,
                             cudaFuncAttributeMaxDynamicSharedMemorySize, SMEM3);
        attr_done = true;
    }

    const int EDGE_GRID = (EE + 255) / 256;
    const int AGG_GRID  = (NN * 32 + 255) / 256;
    const int MLP2_GRID = (NN + 255) / 256;
    const int MLP3_GRID = (NN + 223) / 224;

    // CSR build
    zero_deg_kernel<<<(NN + 255) / 256, 256>>>();
    hist_kernel<<<EDGE_GRID, 256>>>(ei);
    scan_kernel<<<1, 1024>>>();
    fill_kernel<<<EDGE_GRID, 256>>>(ei);

    // block 0
    agg_kernel<<<AGG_GRID, 256>>>(x, agg);
    mlp2_kernel<<<MLP2_GRID, 256, SMEM2>>>(agg, bufA, w1[0], b1[0], w2[0], b2[0]);
    // block 1
    agg_kernel<<<AGG_GRID, 256>>>(bufA, agg);
    mlp2_kernel<<<MLP2_GRID, 256, SMEM2>>>(agg, bufB, w1[1], b1[1], w2[1], b2[1]);
    // block 2 + final linear (fused)
    agg_kernel<<<AGG_GRID, 256>>>(bufB, agg);
    mlp3_kernel<<<MLP3_GRID, 224, SMEM3>>>(agg, out, w1[2], b1[2], w2[2], b2[2], wf, bf);
}

// round 8
// speedup vs baseline: 1.0216x; 1.0216x over previous
#include <cuda_runtime.h>
#include <cstdint>

#define NN 100000
#define DD 64
#define EE 1600000

// Scratch (__device__ globals per allocation-free rule). Zero-initialized at load.
__device__ float g_agg [NN * DD];
__device__ float g_bufA[NN * DD];
__device__ float g_bufB[NN * DD];
__device__ int   g_deg   [NN];     // invariant: zero at kernel_launch entry
__device__ int   g_rowptr[NN + 1];
__device__ int   g_cursor[NN];
__device__ int   g_col   [EE];

typedef unsigned long long ull;
__device__ __forceinline__ ull pack2(float a, float b) {
    ull r; asm("mov.b64 %0, {%1, %2};" : "=l"(r) : "f"(a), "f"(b)); return r;
}
__device__ __forceinline__ void unpack2(ull v, float& a, float& b) {
    asm("mov.b64 {%0, %1}, %2;" : "=f"(a), "=f"(b) : "l"(v));
}
__device__ __forceinline__ ull fma2(ull a, ull b, ull c) {
    ull r; asm("fma.rn.f32x2 %0, %1, %2, %3;" : "=l"(r) : "l"(a), "l"(b), "l"(c)); return r;
}

// ---------------------------------------------------------------------------
// CSR build (3 launches; deg re-zeroed by fill for the NEXT launch)
// ---------------------------------------------------------------------------
__global__ void hist_kernel(const int* __restrict__ ei) {
    int e = blockIdx.x * blockDim.x + threadIdx.x;
    if (e < EE) atomicAdd(&g_deg[ei[EE + e]], 1);
}

__global__ void scan_kernel() {
    __shared__ int sums[1024];
    const int CH = (NN + 1023) / 1024;
    int t = threadIdx.x;
    int base = t * CH;
    int s = 0;
    for (int i = 0; i < CH; i++) {
        int idx = base + i;
        if (idx < NN) s += g_deg[idx];
    }
    sums[t] = s;
    __syncthreads();
    for (int off = 1; off < 1024; off <<= 1) {
        int v = (t >= off) ? sums[t - off] : 0;
        __syncthreads();
        sums[t] += v;
        __syncthreads();
    }
    int prefix = (t == 0) ? 0 : sums[t - 1];
    for (int i = 0; i < CH; i++) {
        int idx = base + i;
        if (idx < NN) {
            int d = g_deg[idx];
            g_rowptr[idx] = prefix;
            g_cursor[idx] = prefix;
            prefix += d;
        }
    }
    if (t == 1023) g_rowptr[NN] = prefix;
}

// fill + restore the deg==0 invariant for the next launch (replaces zero kernel)
__global__ void fill_kernel(const int* __restrict__ ei) {
    int e = blockIdx.x * blockDim.x + threadIdx.x;
    if (e < EE) {
        int d = ei[EE + e];
        int p = atomicAdd(&g_cursor[d], 1);
        g_col[p] = ei[e];
    }
    if (e < NN) g_deg[e] = 0;
}

// ---------------------------------------------------------------------------
// Aggregation gather: warp per dst node, two neighbor rows per LDG.128 warp
// instr (lanes 0-15 -> neighbor j, lanes 16-31 -> neighbor j+1). 16-neighbor
// batches keep 8 independent LDG.128 in flight per lane. Cross-half reduce
// via shfl_xor(16).   out[d] = in[d] + sum_{s in CSR(d)} in[s]
// ---------------------------------------------------------------------------
__global__ __launch_bounds__(256) void agg_kernel(const float* __restrict__ in,
                                                  float* __restrict__ out) {
    int w    = (blockIdx.x * blockDim.x + threadIdx.x) >> 5;
    int lane = threadIdx.x & 31;
    if (w >= NN) return;
    int half = lane >> 4;
    int c    = lane & 15;
    int start = g_rowptr[w];
    int end   = g_rowptr[w + 1];

    const float4* in4 = reinterpret_cast<const float4*>(in);
    float4 a0 = make_float4(0.f, 0.f, 0.f, 0.f);
    float4 a1 = a0, a2 = a0, a3 = a0;
    if (half == 0) a0 = in4[(size_t)w * 16 + c];   // self term, counted once

    for (int i = start; i < end; i += 32) {
        int n   = min(32, end - i);
        int idx = (i + lane < end) ? g_col[i + lane] : 0;
        int j = 0;
        // 16-neighbor batch: 8 paired LDG.128 in flight before any FADD
        for (; j + 16 <= n; j += 16) {
            int s0 = __shfl_sync(0xffffffffu, idx, j      + half);
            int s1 = __shfl_sync(0xffffffffu, idx, j + 2  + half);
            int s2 = __shfl_sync(0xffffffffu, idx, j + 4  + half);
            int s3 = __shfl_sync(0xffffffffu, idx, j + 6  + half);
            int s4 = __shfl_sync(0xffffffffu, idx, j + 8  + half);
            int s5 = __shfl_sync(0xffffffffu, idx, j + 10 + half);
            int s6 = __shfl_sync(0xffffffffu, idx, j + 12 + half);
            int s7 = __shfl_sync(0xffffffffu, idx, j + 14 + half);
            float4 v0 = in4[(size_t)s0 * 16 + c];
            float4 v1 = in4[(size_t)s1 * 16 + c];
            float4 v2 = in4[(size_t)s2 * 16 + c];
            float4 v3 = in4[(size_t)s3 * 16 + c];
            float4 v4 = in4[(size_t)s4 * 16 + c];
            float4 v5 = in4[(size_t)s5 * 16 + c];
            float4 v6 = in4[(size_t)s6 * 16 + c];
            float4 v7 = in4[(size_t)s7 * 16 + c];
            a0.x += v0.x; a0.y += v0.y; a0.z += v0.z; a0.w += v0.w;
            a1.x += v1.x; a1.y += v1.y; a1.z += v1.z; a1.w += v1.w;
            a2.x += v2.x; a2.y += v2.y; a2.z += v2.z; a2.w += v2.w;
            a3.x += v3.x; a3.y += v3.y; a3.z += v3.z; a3.w += v3.w;
            a0.x += v4.x; a0.y += v4.y; a0.z += v4.z; a0.w += v4.w;
            a1.x += v5.x; a1.y += v5.y; a1.z += v5.z; a1.w += v5.w;
            a2.x += v6.x; a2.y += v6.y; a2.z += v6.z; a2.w += v6.w;
            a3.x += v7.x; a3.y += v7.y; a3.z += v7.z; a3.w += v7.w;
        }
        for (; j + 8 <= n; j += 8) {
            int s0 = __shfl_sync(0xffffffffu, idx, j     + half);
            int s1 = __shfl_sync(0xffffffffu, idx, j + 2 + half);
            int s2 = __shfl_sync(0xffffffffu, idx, j + 4 + half);
            int s3 = __shfl_sync(0xffffffffu, idx, j + 6 + half);
            float4 v0 = in4[(size_t)s0 * 16 + c];
            float4 v1 = in4[(size_t)s1 * 16 + c];
            float4 v2 = in4[(size_t)s2 * 16 + c];
            float4 v3 = in4[(size_t)s3 * 16 + c];
            a0.x += v0.x; a0.y += v0.y; a0.z += v0.z; a0.w += v0.w;
            a1.x += v1.x; a1.y += v1.y; a1.z += v1.z; a1.w += v1.w;
            a2.x += v2.x; a2.y += v2.y; a2.z += v2.z; a2.w += v2.w;
            a3.x += v3.x; a3.y += v3.y; a3.z += v3.z; a3.w += v3.w;
        }
        for (; j < n; j += 2) {
            int jj = j + half;
            int s = __shfl_sync(0xffffffffu, idx, (jj < n) ? jj : j);
            if (jj < n) {
                float4 v = in4[(size_t)s * 16 + c];
                a0.x += v.x; a0.y += v.y; a0.z += v.z; a0.w += v.w;
            }
        }
    }
    a0.x += a1.x + a2.x + a3.x;  a0.y += a1.y + a2.y + a3.y;
    a0.z += a1.z + a2.z + a3.z;  a0.w += a1.w + a2.w + a3.w;
    a0.x += __shfl_xor_sync(0xffffffffu, a0.x, 16);
    a0.y += __shfl_xor_sync(0xffffffffu, a0.y, 16);
    a0.z += __shfl_xor_sync(0xffffffffu, a0.z, 16);
    a0.w += __shfl_xor_sync(0xffffffffu, a0.w, 16);
    if (half == 0)
        reinterpret_cast<float4*>(out)[(size_t)w * 16 + c] = a0;
}

// ---------------------------------------------------------------------------
// MLP kernels. Lane owns a full row; rows staged through padded smem.
// Weights read from smem as ulonglong2 (pre-paired for fma2).
// ---------------------------------------------------------------------------
#define STRIDE 66
#define STAGE_WORDS (32 * STRIDE)

__device__ __forceinline__ void half_gemm(const float* __restrict__ ws,
                                          const float* __restrict__ h,
                                          ull* acc, int half) {
#pragma unroll 2
    for (int k = 0; k < DD; k++) {
        float hk = h[k];
        ull h2 = pack2(hk, hk);
#pragma unroll
        for (int jj = 0; jj < 8; jj++) {
            ulonglong2 wv = *reinterpret_cast<const ulonglong2*>(
                ws + k * DD + half * 32 + jj * 4);
            acc[2 * jj]     = fma2(wv.x, h2, acc[2 * jj]);
            acc[2 * jj + 1] = fma2(wv.y, h2, acc[2 * jj + 1]);
        }
    }
}

__device__ __forceinline__ void store_row_relu(float* hrow, ull* mA, ull* mB,
                                               bool relu) {
#pragma unroll
    for (int j = 0; j < 16; j++) {
        float a, b;
        unpack2(mA[j], a, b);
        if (relu) { a = fmaxf(a, 0.f); b = fmaxf(b, 0.f); }
        *reinterpret_cast<float2*>(hrow + 2 * j) = make_float2(a, b);
        unpack2(mB[j], a, b);
        if (relu) { a = fmaxf(a, 0.f); b = fmaxf(b, 0.f); }
        *reinterpret_cast<float2*>(hrow + 32 + 2 * j) = make_float2(a, b);
    }
}

__device__ __forceinline__ void gemm64(const float* ws, const ull* bu,
                                       float* hrow, ull* mA, ull* mB) {
#pragma unroll
    for (int j = 0; j < 16; j++) mA[j] = bu[j];
    half_gemm(ws, hrow, mA, 0);
#pragma unroll
    for (int j = 0; j < 16; j++) mB[j] = bu[16 + j];
    half_gemm(ws, hrow, mB, 1);
}

// Two-GEMM MLP (blocks 0,1): out = relu(relu(in@w1+b1)@w2+b2). 8 warps.
__global__ __launch_bounds__(256, 2) void mlp2_kernel(
        const float* __restrict__ in, float* __restrict__ out,
        const float* __restrict__ w1, const float* __restrict__ b1,
        const float* __restrict__ w2, const float* __restrict__ b2) {
    extern __shared__ float sm[];
    float* ws1 = sm;
    float* ws2 = sm + DD * DD;
    int tid  = threadIdx.x;
    int lane = tid & 31;
    int warp = tid >> 5;
    float* stg = sm + 2 * DD * DD + warp * STAGE_WORDS;

    for (int i = tid; i < DD * DD; i += 256) { ws1[i] = w1[i]; ws2[i] = w2[i]; }

    int rowbase = blockIdx.x * 256 + warp * 32;
#pragma unroll 4
    for (int r = 0; r < 32; r++) {
        int row = rowbase + r;
        float2 v = make_float2(0.f, 0.f);
        if (row < NN)
            v = *reinterpret_cast<const float2*>(in + (size_t)row * DD + 2 * lane);
        *reinterpret_cast<float2*>(stg + r * STRIDE + 2 * lane) = v;
    }
    __syncthreads();

    float* hrow = stg + lane * STRIDE;
    ull mA[16], mB[16];
    gemm64(ws1, reinterpret_cast<const ull*>(b1), hrow, mA, mB);
    store_row_relu(hrow, mA, mB, true);
    gemm64(ws2, reinterpret_cast<const ull*>(b2), hrow, mA, mB);
    store_row_relu(hrow, mA, mB, true);

    __syncwarp();
#pragma unroll 4
    for (int r = 0; r < 32; r++) {
        int row = rowbase + r;
        if (row < NN) {
            float2 v = *reinterpret_cast<const float2*>(stg + r * STRIDE + 2 * lane);
            *reinterpret_cast<float2*>(out + (size_t)row * DD + 2 * lane) = v;
        }
    }
}

// Three-GEMM MLP (block 2 + final linear fused). 7 warps.
__global__ __launch_bounds__(224, 2) void mlp3_kernel(
        const float* __restrict__ in, float* __restrict__ out,
        const float* __restrict__ w1, const float* __restrict__ b1,
        const float* __restrict__ w2, const float* __restrict__ b2,
        const float* __restrict__ w3, const float* __restrict__ b3) {
    extern __shared__ float sm[];
    float* ws1 = sm;
    float* ws2 = sm + DD * DD;
    float* ws3 = sm + 2 * DD * DD;
    int tid  = threadIdx.x;
    int lane = tid & 31;
    int warp = tid >> 5;
    float* stg = sm + 3 * DD * DD + warp * STAGE_WORDS;

    for (int i = tid; i < DD * DD; i += 224) {
        ws1[i] = w1[i]; ws2[i] = w2[i]; ws3[i] = w3[i];
    }

    int rowbase = blockIdx.x * 224 + warp * 32;
#pragma unroll 4
    for (int r = 0; r < 32; r++) {
        int row = rowbase + r;
        float2 v = make_float2(0.f, 0.f);
        if (row < NN)
            v = *reinterpret_cast<const float2*>(in + (size_t)row * DD + 2 * lane);
        *reinterpret_cast<float2*>(stg + r * STRIDE + 2 * lane) = v;
    }
    __syncthreads();

    float* hrow = stg + lane * STRIDE;
    ull mA[16], mB[16];
    gemm64(ws1, reinterpret_cast<const ull*>(b1), hrow, mA, mB);
    store_row_relu(hrow, mA, mB, true);
    gemm64(ws2, reinterpret_cast<const ull*>(b2), hrow, mA, mB);
    store_row_relu(hrow, mA, mB, true);
    gemm64(ws3, reinterpret_cast<const ull*>(b3), hrow, mA, mB);
    store_row_relu(hrow, mA, mB, false);

    __syncwarp();
#pragma unroll 4
    for (int r = 0; r < 32; r++) {
        int row = rowbase + r;
        if (row < NN) {
            float2 v = *reinterpret_cast<const float2*>(stg + r * STRIDE + 2 * lane);
            *reinterpret_cast<float2*>(out + (size_t)row * DD + 2 * lane) = v;
        }
    }
}

// ---------------------------------------------------------------------------
// Launch
// ---------------------------------------------------------------------------
extern "C" void kernel_launch(void* const* d_in, const int* in_sizes, int n_in,
                              void* d_out, int out_size) {
    const float* x  = (const float*)d_in[0];
    const int*   ei = (const int*)d_in[1];
    const float* w1[3] = {(const float*)d_in[2], (const float*)d_in[6],  (const float*)d_in[10]};
    const float* b1[3] = {(const float*)d_in[3], (const float*)d_in[7],  (const float*)d_in[11]};
    const float* w2[3] = {(const float*)d_in[4], (const float*)d_in[8],  (const float*)d_in[12]};
    const float* b2[3] = {(const float*)d_in[5], (const float*)d_in[9],  (const float*)d_in[13]};
    const float* wf = (const float*)d_in[14];
    const float* bf = (const float*)d_in[15];
    float* out = (float*)d_out;

    float *agg, *bufA, *bufB;
    cudaGetSymbolAddress((void**)&agg,  g_agg);
    cudaGetSymbolAddress((void**)&bufA, g_bufA);
    cudaGetSymbolAddress((void**)&bufB, g_bufB);

    const int SMEM2 = (2 * DD * DD + 8 * STAGE_WORDS) * 4;   // ~100.4 KB
    const int SMEM3 = (3 * DD * DD + 7 * STAGE_WORDS) * 4;   // ~108.3 KB
    static bool attr_done = false;
    if (!attr_done) {
        cudaFuncSetAttribute(mlp2_kernel,
                             cudaFuncAttributeMaxDynamicSharedMemorySize, SMEM2);
        cudaFuncSetAttribute(mlp3_kernel,
                             cudaFuncAttributeMaxDynamicSharedMemorySize, SMEM3);
        attr_done = true;
    }

    const int EDGE_GRID = (EE + 511) / 512;
    const int AGG_GRID  = (NN * 32 + 255) / 256;
    const int MLP2_GRID = (NN + 255) / 256;
    const int MLP3_GRID = (NN + 223) / 224;

    // CSR build (deg==0 invariant maintained by fill_kernel of prior launch)
    hist_kernel<<<EDGE_GRID, 512>>>(ei);
    scan_kernel<<<1, 1024>>>();
    fill_kernel<<<EDGE_GRID, 512>>>(ei);

    // block 0
    agg_kernel<<<AGG_GRID, 256>>>(x, agg);
    mlp2_kernel<<<MLP2_GRID, 256, SMEM2>>>(agg, bufA, w1[0], b1[0], w2[0], b2[0]);
    // block 1
    agg_kernel<<<AGG_GRID, 256>>>(bufA, agg);
    mlp2_kernel<<<MLP2_GRID, 256, SMEM2>>>(agg, bufB, w1[1], b1[1], w2[1], b2[1]);
    // block 2 + final linear (fused)
    agg_kernel<<<AGG_GRID, 256>>>(bufB, agg);
    mlp3_kernel<<<MLP3_GRID, 224, SMEM3>>>(agg, out, w1[2], b1[2], w2[2], b2[2], wf, bf);
}